// round 7
// baseline (speedup 1.0000x reference)
#include <cuda_runtime.h>

// Caps_Layer: B=128, N=512, D=300, NC=10, DC=64, ROUTINGS=5  (fused, 1 CTA/batch)
// NT=960 (30 warps). u = x@W never materialized. Per iteration:
//   P2: o_raw[m] = sum_d y[i,d] W[d,m] (6 d-slices x 160 m-quads); squash -> o
//   P3: v[i,d] = sum_k o[i,k] Wt[i*64+k, d]   (pre-transposed W)
//   XPASS tiled over j (32/tile, double-buffered cp.async):
//       B: 30 warps = 2 i-halves x 15 d-chunks(20d), acc[5]
//       softmax (512 thr, shfl-16), c stored as 6-u64 aligned splat groups
//       C: 600 thr = 2 i-halves x 2 j-groups x 150 d-pairs, yacc[5] in regs
// Iteration 0: c uniform -> y = 0.1*colsum(x).

#define NN 512
#define DD 300
#define NC 10
#define DC 64
#define MM 640
#define BB 128
#define NT 960
#define TJ 32
#define NTILE 16
#define AR_BUF (TJ * DD)        // 9600 floats per buffer

#define OFF_AR  0               // 2 buffers = 19200
#define OFF_V   19200           // 3000
#define OFF_Y   22200           // 3000
#define OFF_YP  25200           // 6000 (2 j-group partials)
#define OFF_BP  31200           // 5760 (30 warps * 192)  (P2 scratch 6*640, it0 600)
#define OFF_C2  36960           // 768 floats = 384 u64 (32 j * 2 ih * 6-u64 groups)
#define OFF_O   37728           // 640
#define OFF_NRM 38368           // 16
#define SMEM_FLOATS 38384
#define SMEM_BYTES (SMEM_FLOATS * 4)

typedef unsigned long long u64;
struct u64x2_t { u64 x, y; };

__device__ float Wt_g[MM * DD];   // W transposed: Wt[m*300 + d]

__device__ __forceinline__ void fma2(u64& acc, u64 a, u64 b) {
    asm("fma.rn.f32x2 %0, %1, %2, %0;" : "+l"(acc) : "l"(a), "l"(b));
}
__device__ __forceinline__ u64 splat2(float f) {
    u64 r; asm("mov.b64 %0, {%1,%1};" : "=l"(r) : "f"(f)); return r;
}
__device__ __forceinline__ float fold2(u64 v) {
    float lo, hi; asm("mov.b64 {%0,%1}, %2;" : "=f"(lo), "=f"(hi) : "l"(v)); return lo + hi;
}
__device__ __forceinline__ void cp16(void* smem_dst, const void* gsrc) {
    unsigned sa = (unsigned)__cvta_generic_to_shared(smem_dst);
    asm volatile("cp.async.cg.shared.global [%0], [%1], 16;" :: "r"(sa), "l"(gsrc));
}
__device__ __forceinline__ void cp_commit() { asm volatile("cp.async.commit_group;"); }
template <int N> __device__ __forceinline__ void cp_wait() {
    asm volatile("cp.async.wait_group %0;" :: "n"(N));
}

// ---------------- prologue: W[300][640] -> Wt[640][300] ----------------
__global__ void transpose_W(const float* __restrict__ W)
{
    __shared__ float tl[32][33];
    const int tx = threadIdx.x, ty = threadIdx.y;     // 32 x 8
    const int m0 = blockIdx.x * 32, d0 = blockIdx.y * 32;
    #pragma unroll
    for (int k = 0; k < 4; ++k) {
        const int d = d0 + ty + k * 8;
        if (d < DD) tl[ty + k * 8][tx] = W[(size_t)d * MM + m0 + tx];
    }
    __syncthreads();
    #pragma unroll
    for (int k = 0; k < 4; ++k) {
        const int m = m0 + ty + k * 8;
        const int d = d0 + tx;
        if (d < DD) Wt_g[(size_t)m * DD + d] = tl[tx][ty + k * 8];
    }
}

__global__ __launch_bounds__(NT, 1)
void caps_kernel(const float* __restrict__ x,
                 const float* __restrict__ W,
                 float* __restrict__ out)
{
    extern __shared__ float sm[];
    const int b    = blockIdx.x;
    const int t    = threadIdx.x;
    const int w    = t >> 5;
    const int lane = t & 31;
    const float* __restrict__ xb = x + (size_t)b * NN * DD;

    float* v_s  = sm + OFF_V;
    float* y_s  = sm + OFF_Y;
    float* yp   = sm + OFF_YP;
    float* bp   = sm + OFF_BP;
    u64*   c2   = (u64*)(sm + OFF_C2);
    float* o_s  = sm + OFF_O;
    float* nrm  = sm + OFF_NRM;

    // B-phase mapping: warp = (i-half, d-chunk of 20)
    const int ihB = w / 15;             // 0..1
    const int dBB = (w - ihB * 15) * 20;
    const int i0B = ihB * 5;

    // C-phase mapping (t < 600): (i-half, j-group, d-pair)
    const int ihC = t / 300;
    const int remC = t - ihC * 300;
    const int jgC = remC / 150;
    const int d0c = (remC - jgC * 150) * 2;

    // ---- iteration 0: y[i,d] = 0.1 * colsum_d(x) ----
    if (t < 600) {
        const int g = t / 300, d = t - g * 300;
        const float* __restrict__ xp = xb + (size_t)(g * 256) * DD + d;
        float a0 = 0.f, a1 = 0.f, a2 = 0.f, a3 = 0.f;
        for (int j = 0; j < 256; j += 4) {
            a0 += xp[(j + 0) * DD]; a1 += xp[(j + 1) * DD];
            a2 += xp[(j + 2) * DD]; a3 += xp[(j + 3) * DD];
        }
        bp[g * 300 + d] = (a0 + a1) + (a2 + a3);
    }
    __syncthreads();
    for (int idx = t; idx < NC * DD; idx += NT) {
        const int d = idx % DD;
        y_s[idx] = 0.1f * (bp[d] + bp[300 + d]);
    }
    __syncthreads();

    for (int r = 0; r < 5; ++r) {
        // ---------------- P2: o_raw[m] = sum_d y[i,d] W[d,m] ----------------
        {
            const int ds  = t / 160;            // d-slice 0..5
            const int m4  = (t - ds * 160) * 4; // 4 consecutive m
            const int ci  = m4 >> 6;
            const int d0  = ds * 50;
            const float* __restrict__ ypt = y_s + ci * DD;
            u64 a01 = 0ull, a23 = 0ull;
            #pragma unroll 5
            for (int d = d0; d < d0 + 50; ++d) {
                const u64x2_t w4 = *(const u64x2_t*)(W + (size_t)d * MM + m4);
                const u64 ys = splat2(ypt[d]);
                fma2(a01, w4.x, ys); fma2(a23, w4.y, ys);
            }
            *(u64*)(bp + ds * MM + m4)     = a01;
            *(u64*)(bp + ds * MM + m4 + 2) = a23;
        }
        __syncthreads();
        if (t < 640) {
            float o = 0.f;
            #pragma unroll
            for (int s = 0; s < 6; ++s) o += bp[s * MM + t];
            o_s[t] = o;
        }
        __syncthreads();
        if (t < 320) {   // squash norms: 10 warps, shuffle reduce
            const int i = t >> 5;
            const float v0 = o_s[i * DC + lane];
            const float v1 = o_s[i * DC + 32 + lane];
            float s = v0 * v0 + v1 * v1;
            #pragma unroll
            for (int k = 16; k > 0; k >>= 1) s += __shfl_xor_sync(0xffffffffu, s, k);
            if (lane == 0) nrm[i] = rsqrtf(s + 1e-7f);
        }
        __syncthreads();
        if (t < 640) {
            const float ov = o_s[t] * nrm[t >> 6];
            o_s[t] = ov;
            if (r == 4) out[(size_t)b * MM + t] = ov;
        }
        if (r == 4) break;
        __syncthreads();

        // ---------------- P3: v[i,d] = sum_k o[i,k] Wt[i*64+k, d] ----------------
        for (int idx = t; idx < NC * 150; idx += NT) {
            const int i  = idx / 150;
            const int d0 = (idx - i * 150) * 2;
            const float* __restrict__ ob = o_s + i * DC;
            const float* __restrict__ wt = Wt_g + (size_t)i * DC * DD + d0;
            u64 acc = 0ull;
            #pragma unroll 8
            for (int k = 0; k < DC; ++k)
                fma2(acc, *(const u64*)(wt + (size_t)k * DD), splat2(ob[k]));
            *(u64*)(v_s + i * DD + d0) = acc;
        }
        __syncthreads();

        // ---------------- XPASS ----------------
        u64 yacc[5];
        #pragma unroll
        for (int i = 0; i < 5; ++i) yacc[i] = 0ull;

        // prologue: tile 0
        for (int idx = t; idx < AR_BUF / 4; idx += NT)
            cp16(sm + OFF_AR + idx * 4, xb + idx * 4);
        cp_commit();

        for (int tile = 0; tile < NTILE; ++tile) {
            if (tile < NTILE - 1) {
                const int nb = (tile + 1) & 1;
                const float* gs = xb + (size_t)(tile + 1) * TJ * DD;
                for (int idx = t; idx < AR_BUF / 4; idx += NT)
                    cp16(sm + OFF_AR + nb * AR_BUF + idx * 4, gs + idx * 4);
                cp_commit(); cp_wait<1>();
            } else {
                cp_wait<0>();
            }
            __syncthreads();
            const float* xs = sm + OFF_AR + (tile & 1) * AR_BUF;

            // ---- B: partial b[i0B..i0B+4, j=lane] over this warp's 20-d chunk ----
            {
                u64 acc[5];
                #pragma unroll
                for (int il = 0; il < 5; ++il) acc[il] = 0ull;
                const float* xrow = xs + lane * DD + dBB;
                #pragma unroll
                for (int sub = 0; sub < 2; ++sub) {
                    u64 xv[5];
                    #pragma unroll
                    for (int p = 0; p < 5; ++p)
                        xv[p] = *(const u64*)(xrow + sub * 10 + 2 * p);
                    #pragma unroll
                    for (int il = 0; il < 5; ++il) {
                        const float* vb = v_s + (i0B + il) * DD + dBB + sub * 10;
                        #pragma unroll
                        for (int p = 0; p < 5; ++p)
                            fma2(acc[il], xv[p], *(const u64*)(vb + 2 * p));
                    }
                }
                #pragma unroll
                for (int il = 0; il < 5; ++il)
                    bp[w * 192 + lane * 6 + il] = fold2(acc[il]);
            }
            __syncthreads();

            // ---- softmax over i per j (512 thr, shfl within 16-lane groups) ----
            if (t < 512) {
                const int j = t >> 4, ii = t & 15;
                float s;
                if (ii < NC) {
                    const int ih = ii / 5, il = ii - ih * 5;
                    s = 0.f;
                    #pragma unroll
                    for (int dc = 0; dc < 15; ++dc)
                        s += bp[(ih * 15 + dc) * 192 + j * 6 + il];
                } else s = -1e30f;
                float m = s;
                #pragma unroll
                for (int k = 8; k > 0; k >>= 1)
                    m = fmaxf(m, __shfl_xor_sync(0xffffffffu, m, k, 16));
                const float e = __expf(s - m);
                float su = e;
                #pragma unroll
                for (int k = 8; k > 0; k >>= 1)
                    su += __shfl_xor_sync(0xffffffffu, su, k, 16);
                if (ii < NC) {
                    const int ih = ii / 5, il = ii - ih * 5;
                    c2[(j * 2 + ih) * 6 + il] = splat2(e * (1.0f / su));
                }
            }
            __syncthreads();

            // ---- C: yacc[il] += c[i0C+il, j] * x[j, d0c..d0c+1] (16 j) ----
            if (t < 600) {
                const int j0 = jgC * 16;
                #pragma unroll
                for (int jj = 0; jj < 16; ++jj) {
                    const int j = j0 + jj;
                    const u64 xv = *(const u64*)(xs + j * DD + d0c);
                    const u64* cb = c2 + (j * 2 + ihC) * 6;
                    const u64x2_t c01 = *(const u64x2_t*)(cb);
                    const u64x2_t c23 = *(const u64x2_t*)(cb + 2);
                    const u64     c4  = cb[4];
                    fma2(yacc[0], xv, c01.x);
                    fma2(yacc[1], xv, c01.y);
                    fma2(yacc[2], xv, c23.x);
                    fma2(yacc[3], xv, c23.y);
                    fma2(yacc[4], xv, c4);
                }
            }
            __syncthreads();
        }

        // flush yacc -> yp (2 j-group partials), reduce into y
        if (t < 600) {
            #pragma unroll
            for (int il = 0; il < 5; ++il)
                *(u64*)(yp + jgC * 3000 + (ihC * 5 + il) * DD + d0c) = yacc[il];
        }
        __syncthreads();
        for (int idx = t; idx < NC * DD; idx += NT)
            y_s[idx] = yp[idx] + yp[3000 + idx];
        __syncthreads();
    }
}

extern "C" void kernel_launch(void* const* d_in, const int* in_sizes, int n_in,
                              void* d_out, int out_size)
{
    const float* x = (const float*)d_in[0];
    const float* W = (const float*)d_in[1];
    if (n_in >= 2 && in_sizes[0] < in_sizes[1]) {
        x = (const float*)d_in[1];
        W = (const float*)d_in[0];
    }
    float* out = (float*)d_out;

    static int attr_done = 0;
    if (!attr_done) {
        cudaFuncSetAttribute(caps_kernel, cudaFuncAttributeMaxDynamicSharedMemorySize,
                             SMEM_BYTES);
        attr_done = 1;
    }

    dim3 tb(32, 8);
    dim3 tg(MM / 32, (DD + 31) / 32);
    transpose_W<<<tg, tb>>>(W);
    caps_kernel<<<BB, NT, SMEM_BYTES>>>(x, W, out);
}

// round 8
// speedup vs baseline: 1.2055x; 1.2055x over previous
#include <cuda_runtime.h>

// Caps_Layer: B=128, N=512, D=300, NC=10, DC=64, ROUTINGS=5  (fused, 1 CTA/batch)
// u = x@W never materialized. Per iteration:
//   P2: o_raw[m] = sum_d y[i,d] W[d,m] ; squash -> o    (as R3)
//   P3: v[i,d] = sum_k o[i,k] Wt[i*64+k,d]              (pre-transposed W, as R3)
//   XPASS (warp-specialized pipeline over 16 j-tiles of 32):
//     wg0 (warps 0-9):  prefetch x tiles (3-buffer ring) ; B(k): b=x*v
//                       (10 warps x 32d chunks, u64x2) ; softmax(k) -> c[parity]
//     wg1 (warps 10-19): C(k): y += c*x (register yacc, 2 j-groups)
//     handoff: bar.arrive/sync id1 (c ready), id2 (C done, backpressure), id3 wg0-local.

#define NN 512
#define DD 300
#define NC 10
#define DC 64
#define MM 640
#define BB 128
#define NT 640
#define TJ 32
#define NTILE 16
#define AR_BUF (TJ * DD)          // 9600 floats per buffer

#define OFF_AR  0                 // 3 buffers = 28800
#define OFF_V   28800             // 3000
#define OFF_Y   31800             // 3000
#define OFF_YP  34800             // 6000 (2 j-group partials)
#define OFF_BP  40800             // 3520 (10 warps * 352; also P2 scratch 2560, it0 600)
#define OFF_C   44320             // 2 parities * 384 = 768  (c[j*12 + i], plain floats)
#define OFF_O   45088             // 640
#define OFF_NRM 45728             // 16
#define SMEM_FLOATS 45744
#define SMEM_BYTES (SMEM_FLOATS * 4)

typedef unsigned long long u64;
struct u64x2_t { u64 x, y; };

__device__ float Wt_g[MM * DD];   // W transposed: Wt[m*300 + d]

__device__ __forceinline__ void fma2(u64& acc, u64 a, u64 b) {
    asm("fma.rn.f32x2 %0, %1, %2, %0;" : "+l"(acc) : "l"(a), "l"(b));
}
__device__ __forceinline__ u64 splat2(float f) {
    u64 r; asm("mov.b64 %0, {%1,%1};" : "=l"(r) : "f"(f)); return r;
}
__device__ __forceinline__ float fold2(u64 v) {
    float lo, hi; asm("mov.b64 {%0,%1}, %2;" : "=f"(lo), "=f"(hi) : "l"(v)); return lo + hi;
}
__device__ __forceinline__ void cp16(void* smem_dst, const void* gsrc) {
    unsigned sa = (unsigned)__cvta_generic_to_shared(smem_dst);
    asm volatile("cp.async.cg.shared.global [%0], [%1], 16;" :: "r"(sa), "l"(gsrc));
}
__device__ __forceinline__ void cp_commit() { asm volatile("cp.async.commit_group;"); }
template <int N> __device__ __forceinline__ void cp_wait() {
    asm volatile("cp.async.wait_group %0;" :: "n"(N));
}
__device__ __forceinline__ void bar_arrive(int id, int cnt) {
    asm volatile("bar.arrive %0, %1;" :: "r"(id), "r"(cnt) : "memory");
}
__device__ __forceinline__ void bar_sync(int id, int cnt) {
    asm volatile("bar.sync %0, %1;" :: "r"(id), "r"(cnt) : "memory");
}

// ---------------- prologue: W[300][640] -> Wt[640][300] ----------------
__global__ void transpose_W(const float* __restrict__ W)
{
    __shared__ float tl[32][33];
    const int tx = threadIdx.x, ty = threadIdx.y;     // 32 x 8
    const int m0 = blockIdx.x * 32, d0 = blockIdx.y * 32;
    #pragma unroll
    for (int k = 0; k < 4; ++k) {
        const int d = d0 + ty + k * 8;
        if (d < DD) tl[ty + k * 8][tx] = W[(size_t)d * MM + m0 + tx];
    }
    __syncthreads();
    #pragma unroll
    for (int k = 0; k < 4; ++k) {
        const int m = m0 + ty + k * 8;
        const int d = d0 + tx;
        if (d < DD) Wt_g[(size_t)m * DD + d] = tl[tx][ty + k * 8];
    }
}

__global__ __launch_bounds__(NT, 1)
void caps_kernel(const float* __restrict__ x,
                 const float* __restrict__ W,
                 float* __restrict__ out)
{
    extern __shared__ float sm[];
    const int b    = blockIdx.x;
    const int t    = threadIdx.x;
    const int w    = t >> 5;
    const int lane = t & 31;
    const float* __restrict__ xb = x + (size_t)b * NN * DD;

    float* v_s  = sm + OFF_V;
    float* y_s  = sm + OFF_Y;
    float* yp   = sm + OFF_YP;
    float* bp   = sm + OFF_BP;
    float* o_s  = sm + OFF_O;
    float* nrm  = sm + OFF_NRM;

    // ---- iteration 0: y[i,d] = 0.1 * colsum_d(x) ----
    if (t < 600) {
        const int g = t / 300, d = t - g * 300;
        const float* __restrict__ xp = xb + (size_t)(g * 256) * DD + d;
        float a0 = 0.f, a1 = 0.f, a2 = 0.f, a3 = 0.f;
        for (int j = 0; j < 256; j += 4) {
            a0 += xp[(j + 0) * DD]; a1 += xp[(j + 1) * DD];
            a2 += xp[(j + 2) * DD]; a3 += xp[(j + 3) * DD];
        }
        bp[g * 300 + d] = (a0 + a1) + (a2 + a3);
    }
    __syncthreads();
    for (int idx = t; idx < NC * DD; idx += NT) {
        const int d = idx % DD;
        y_s[idx] = 0.1f * (bp[d] + bp[300 + d]);
    }
    __syncthreads();

    for (int r = 0; r < 5; ++r) {
        // ---------------- P2: o_raw[m] = sum_d y[i,d] W[d,m] ----------------
        {
            const int ds  = t / 160;            // d-slice 0..3
            const int m4  = (t - ds * 160) * 4; // 4 consecutive m
            const int ci  = m4 >> 6;
            const int d0  = ds * 75;
            const float* __restrict__ ypt = y_s + ci * DD;
            u64 a01 = 0ull, a23 = 0ull;
            #pragma unroll 5
            for (int d = d0; d < d0 + 75; ++d) {
                const u64x2_t w4 = *(const u64x2_t*)(W + (size_t)d * MM + m4);
                const u64 ys = splat2(ypt[d]);
                fma2(a01, w4.x, ys); fma2(a23, w4.y, ys);
            }
            *(u64*)(bp + ds * MM + m4)     = a01;
            *(u64*)(bp + ds * MM + m4 + 2) = a23;
        }
        __syncthreads();
        o_s[t] = bp[t] + bp[MM + t] + bp[2 * MM + t] + bp[3 * MM + t];
        __syncthreads();
        if (t < 320) {   // squash norms
            const int i = t >> 5;
            const float v0 = o_s[i * DC + lane];
            const float v1 = o_s[i * DC + 32 + lane];
            float s = v0 * v0 + v1 * v1;
            #pragma unroll
            for (int k = 16; k > 0; k >>= 1) s += __shfl_xor_sync(0xffffffffu, s, k);
            if (lane == 0) nrm[i] = rsqrtf(s + 1e-7f);
        }
        __syncthreads();
        const float ov = o_s[t] * nrm[t >> 6];
        o_s[t] = ov;
        if (r == 4) { out[(size_t)b * MM + t] = ov; break; }
        __syncthreads();

        // ---------------- P3: v[i,d] = sum_k o[i,k] Wt[i*64+k, d] ----------------
        for (int idx = t; idx < NC * 150; idx += NT) {
            const int i  = idx / 150;
            const int d0 = (idx - i * 150) * 2;
            const float* __restrict__ ob = o_s + i * DC;
            const float* __restrict__ wt = Wt_g + (size_t)i * DC * DD + d0;
            u64 acc = 0ull;
            #pragma unroll 8
            for (int k = 0; k < DC; ++k)
                fma2(acc, *(const u64*)(wt + (size_t)k * DD), splat2(ob[k]));
            *(u64*)(v_s + i * DD + d0) = acc;
        }
        __syncthreads();

        // ---------------- XPASS: warp-specialized pipeline ----------------
        if (t < 320) {
            // ===== wg0: prefetch + B + softmax =====
            // prologue: tiles 0, 1
            for (int idx = t; idx < AR_BUF / 4; idx += 320)
                cp16(sm + OFF_AR + idx * 4, xb + idx * 4);
            cp_commit();
            for (int idx = t; idx < AR_BUF / 4; idx += 320)
                cp16(sm + OFF_AR + AR_BUF + idx * 4, xb + AR_BUF + idx * 4);
            cp_commit();

            const int dB  = (w < 9) ? w * 32 : 288;
            const int n16 = (w < 9) ? 8 : 3;

            for (int k = 0; k < NTILE; ++k) {
                if (k == NTILE - 1) cp_wait<0>(); else cp_wait<1>();
                bar_sync(3, 320);
                const float* xs = sm + OFF_AR + (k % 3) * AR_BUF;

                // ---- B: b[i, j=lane] over this warp's d-chunk ----
                {
                    u64 acc[NC];
                    #pragma unroll
                    for (int i = 0; i < NC; ++i) acc[i] = 0ull;
                    const float* xrow = xs + lane * DD + dB;
                    for (int s = 0; s < n16; ++s) {
                        const u64x2_t xv = *(const u64x2_t*)(xrow + s * 4);
                        #pragma unroll
                        for (int i = 0; i < NC; ++i) {
                            const u64x2_t vv = *(const u64x2_t*)(v_s + i * DD + dB + s * 4);
                            fma2(acc[i], xv.x, vv.x);
                            fma2(acc[i], xv.y, vv.y);
                        }
                    }
                    #pragma unroll
                    for (int i = 0; i < NC; ++i)
                        bp[w * 352 + lane * 11 + i] = fold2(acc[i]);
                }
                bar_sync(3, 320);

                // ---- softmax over i per j (2 rounds of 20 16-lane groups) ----
                {
                    float* cb = sm + OFF_C + (k & 1) * 384;
                    #pragma unroll
                    for (int rd = 0; rd < 2; ++rd) {
                        if (rd == 1 && t >= 192) break;   // warp-aligned exit
                        const int j  = rd * 20 + (t >> 4);
                        const int ii = t & 15;
                        float s;
                        if (ii < NC) {
                            s = 0.f;
                            #pragma unroll
                            for (int ww = 0; ww < 10; ++ww)
                                s += bp[ww * 352 + j * 11 + ii];
                        } else s = -1e30f;
                        float m = s;
                        #pragma unroll
                        for (int kk = 8; kk > 0; kk >>= 1)
                            m = fmaxf(m, __shfl_xor_sync(0xffffffffu, m, kk, 16));
                        const float e = __expf(s - m);
                        float su = e;
                        #pragma unroll
                        for (int kk = 8; kk > 0; kk >>= 1)
                            su += __shfl_xor_sync(0xffffffffu, su, kk, 16);
                        if (ii < NC) cb[j * 12 + ii] = e * (1.0f / su);
                    }
                }
                bar_arrive(1, 640);                 // c(k) + x(k) ready for wg1
                if (k >= 1) bar_sync(2, 640);       // wait C(k-1): frees buf (k+2)%3, c parity
                if (k + 2 < NTILE) {
                    const float* gs = xb + (size_t)(k + 2) * AR_BUF;
                    float* dst = sm + OFF_AR + ((k + 2) % 3) * AR_BUF;
                    for (int idx = t; idx < AR_BUF / 4; idx += 320)
                        cp16(dst + idx * 4, gs + idx * 4);
                    cp_commit();
                }
            }
            bar_sync(2, 640);                       // consume C(last) arrive
        } else {
            // ===== wg1: C phase =====
            const int t2  = t - 320;                // 0..319, active < 300
            const int jg  = t2 / 150;
            const int d0c = (t2 - jg * 150) * 2;
            const int j0  = jg * 16;
            u64 yacc[NC];
            #pragma unroll
            for (int i = 0; i < NC; ++i) yacc[i] = 0ull;

            for (int k = 0; k < NTILE; ++k) {
                bar_sync(1, 640);                   // wait B+softmax(k)
                const float* xs = sm + OFF_AR + (k % 3) * AR_BUF;
                const float* cb = sm + OFF_C + (k & 1) * 384;
                if (t2 < 300) {
                    #pragma unroll
                    for (int jj = 0; jj < 16; ++jj) {
                        const int j = j0 + jj;
                        const u64 xv = *(const u64*)(xs + j * DD + d0c);
                        const float4 c0 = *(const float4*)(cb + j * 12);
                        const float4 c1 = *(const float4*)(cb + j * 12 + 4);
                        const float2 c2v = *(const float2*)(cb + j * 12 + 8);
                        fma2(yacc[0], xv, splat2(c0.x));
                        fma2(yacc[1], xv, splat2(c0.y));
                        fma2(yacc[2], xv, splat2(c0.z));
                        fma2(yacc[3], xv, splat2(c0.w));
                        fma2(yacc[4], xv, splat2(c1.x));
                        fma2(yacc[5], xv, splat2(c1.y));
                        fma2(yacc[6], xv, splat2(c1.z));
                        fma2(yacc[7], xv, splat2(c1.w));
                        fma2(yacc[8], xv, splat2(c2v.x));
                        fma2(yacc[9], xv, splat2(c2v.y));
                    }
                }
                bar_arrive(2, 640);                 // C(k) done
            }
            if (t2 < 300) {
                #pragma unroll
                for (int i = 0; i < NC; ++i)
                    *(u64*)(yp + jg * 3000 + i * DD + d0c) = yacc[i];
            }
        }
        __syncthreads();
        for (int idx = t; idx < NC * DD; idx += NT)
            y_s[idx] = yp[idx] + yp[3000 + idx];
        __syncthreads();
    }
}

extern "C" void kernel_launch(void* const* d_in, const int* in_sizes, int n_in,
                              void* d_out, int out_size)
{
    const float* x = (const float*)d_in[0];
    const float* W = (const float*)d_in[1];
    if (n_in >= 2 && in_sizes[0] < in_sizes[1]) {
        x = (const float*)d_in[1];
        W = (const float*)d_in[0];
    }
    float* out = (float*)d_out;

    static int attr_done = 0;
    if (!attr_done) {
        cudaFuncSetAttribute(caps_kernel, cudaFuncAttributeMaxDynamicSharedMemorySize,
                             SMEM_BYTES);
        attr_done = 1;
    }

    dim3 tb(32, 8);
    dim3 tg(MM / 32, (DD + 31) / 32);
    transpose_W<<<tg, tb>>>(W);
    caps_kernel<<<BB, NT, SMEM_BYTES>>>(x, W, out);
}

// round 9
// speedup vs baseline: 1.2810x; 1.0627x over previous
#include <cuda_runtime.h>

// Caps_Layer: B=128, N=512, D=300, NC=10, DC=64, ROUTINGS=5  (fused, 1 CTA/batch)
// u = x@W never materialized. Per iteration:
//   P2: o_raw[m] = sum_d y[i,d] W[d,m] ; squash -> o
//   P3: v[i,d] = sum_k o[i,k] Wt[i*64+k,d]              (pre-transposed W)
//   XPASS (warp-specialized pipeline over 16 j-tiles of 32):
//     wg0 (warps 0-9):  prefetch x tiles (3-buffer ring); B(k): b=x*v -> bp[k&1]
//     wg1 (warps 10-19): softmax(k) (bp[k&1] -> cb) ; C(k): y += c*x (reg yacc)
//     bars: id1 B(k) done -> wg1 ; id2 C(k) done -> wg0 backpressure ;
//           id3 wg0-local (cp visibility) ; id4 wg1-local (cb visibility).

#define NN 512
#define DD 300
#define NC 10
#define DC 64
#define MM 640
#define BB 128
#define NT 640
#define TJ 32
#define NTILE 16
#define AR_BUF (TJ * DD)          // 9600 floats per buffer

#define OFF_AR  0                 // 3 buffers = 28800
#define OFF_V   28800             // 3000
#define OFF_Y   31800             // 3000
#define OFF_YP  34800             // 6000 (2 j-group partials)
#define OFF_BP  40800             // 2 x 3520 = 7040 (parity; also P2 scratch, it0)
#define OFF_C   47840             // 384  (c[j*12 + i], plain floats)
#define OFF_O   48224             // 640
#define OFF_NRM 48864             // 16
#define SMEM_FLOATS 48880
#define SMEM_BYTES (SMEM_FLOATS * 4)

typedef unsigned long long u64;
struct u64x2_t { u64 x, y; };

__device__ float Wt_g[MM * DD];   // W transposed: Wt[m*300 + d]

__device__ __forceinline__ void fma2(u64& acc, u64 a, u64 b) {
    asm("fma.rn.f32x2 %0, %1, %2, %0;" : "+l"(acc) : "l"(a), "l"(b));
}
__device__ __forceinline__ u64 splat2(float f) {
    u64 r; asm("mov.b64 %0, {%1,%1};" : "=l"(r) : "f"(f)); return r;
}
__device__ __forceinline__ float fold2(u64 v) {
    float lo, hi; asm("mov.b64 {%0,%1}, %2;" : "=f"(lo), "=f"(hi) : "l"(v)); return lo + hi;
}
__device__ __forceinline__ void cp16(void* smem_dst, const void* gsrc) {
    unsigned sa = (unsigned)__cvta_generic_to_shared(smem_dst);
    asm volatile("cp.async.cg.shared.global [%0], [%1], 16;" :: "r"(sa), "l"(gsrc));
}
__device__ __forceinline__ void cp_commit() { asm volatile("cp.async.commit_group;"); }
template <int N> __device__ __forceinline__ void cp_wait() {
    asm volatile("cp.async.wait_group %0;" :: "n"(N));
}
__device__ __forceinline__ void bar_arrive(int id, int cnt) {
    asm volatile("bar.arrive %0, %1;" :: "r"(id), "r"(cnt) : "memory");
}
__device__ __forceinline__ void bar_sync(int id, int cnt) {
    asm volatile("bar.sync %0, %1;" :: "r"(id), "r"(cnt) : "memory");
}

// ---------------- prologue: W[300][640] -> Wt[640][300] ----------------
__global__ void transpose_W(const float* __restrict__ W)
{
    __shared__ float tl[32][33];
    const int tx = threadIdx.x, ty = threadIdx.y;     // 32 x 8
    const int m0 = blockIdx.x * 32, d0 = blockIdx.y * 32;
    #pragma unroll
    for (int k = 0; k < 4; ++k) {
        const int d = d0 + ty + k * 8;
        if (d < DD) tl[ty + k * 8][tx] = W[(size_t)d * MM + m0 + tx];
    }
    __syncthreads();
    #pragma unroll
    for (int k = 0; k < 4; ++k) {
        const int m = m0 + ty + k * 8;
        const int d = d0 + tx;
        if (d < DD) Wt_g[(size_t)m * DD + d] = tl[tx][ty + k * 8];
    }
}

__global__ __launch_bounds__(NT, 1)
void caps_kernel(const float* __restrict__ x,
                 const float* __restrict__ W,
                 float* __restrict__ out)
{
    extern __shared__ float sm[];
    const int b    = blockIdx.x;
    const int t    = threadIdx.x;
    const int w    = t >> 5;
    const int lane = t & 31;
    const float* __restrict__ xb = x + (size_t)b * NN * DD;

    float* v_s  = sm + OFF_V;
    float* y_s  = sm + OFF_Y;
    float* yp   = sm + OFF_YP;
    float* bp   = sm + OFF_BP;
    float* cb   = sm + OFF_C;
    float* o_s  = sm + OFF_O;
    float* nrm  = sm + OFF_NRM;

    // ---- iteration 0: y[i,d] = 0.1 * colsum_d(x) ----
    if (t < 600) {
        const int g = t / 300, d = t - g * 300;
        const float* __restrict__ xp = xb + (size_t)(g * 256) * DD + d;
        float a0 = 0.f, a1 = 0.f, a2 = 0.f, a3 = 0.f;
        for (int j = 0; j < 256; j += 4) {
            a0 += xp[(j + 0) * DD]; a1 += xp[(j + 1) * DD];
            a2 += xp[(j + 2) * DD]; a3 += xp[(j + 3) * DD];
        }
        bp[g * 300 + d] = (a0 + a1) + (a2 + a3);
    }
    __syncthreads();
    for (int idx = t; idx < NC * DD; idx += NT) {
        const int d = idx % DD;
        y_s[idx] = 0.1f * (bp[d] + bp[300 + d]);
    }
    __syncthreads();

    for (int r = 0; r < 5; ++r) {
        // ---------------- P2: o_raw[m] = sum_d y[i,d] W[d,m] ----------------
        {
            const int ds  = t / 160;            // d-slice 0..3
            const int m4  = (t - ds * 160) * 4; // 4 consecutive m
            const int ci  = m4 >> 6;
            const int d0  = ds * 75;
            const float* __restrict__ ypt = y_s + ci * DD;
            u64 a01 = 0ull, a23 = 0ull;
            #pragma unroll 5
            for (int d = d0; d < d0 + 75; ++d) {
                const u64x2_t w4 = *(const u64x2_t*)(W + (size_t)d * MM + m4);
                const u64 ys = splat2(ypt[d]);
                fma2(a01, w4.x, ys); fma2(a23, w4.y, ys);
            }
            *(u64*)(bp + ds * MM + m4)     = a01;
            *(u64*)(bp + ds * MM + m4 + 2) = a23;
        }
        __syncthreads();
        o_s[t] = bp[t] + bp[MM + t] + bp[2 * MM + t] + bp[3 * MM + t];
        __syncthreads();
        if (t < 320) {   // squash norms
            const int i = t >> 5;
            const float v0 = o_s[i * DC + lane];
            const float v1 = o_s[i * DC + 32 + lane];
            float s = v0 * v0 + v1 * v1;
            #pragma unroll
            for (int k = 16; k > 0; k >>= 1) s += __shfl_xor_sync(0xffffffffu, s, k);
            if (lane == 0) nrm[i] = rsqrtf(s + 1e-7f);
        }
        __syncthreads();
        const float ov = o_s[t] * nrm[t >> 6];
        o_s[t] = ov;
        if (r == 4) { out[(size_t)b * MM + t] = ov; break; }
        __syncthreads();

        // ---------------- P3: v[i,d] = sum_k o[i,k] Wt[i*64+k, d] ----------------
        for (int idx = t; idx < NC * 150; idx += NT) {
            const int i  = idx / 150;
            const int d0 = (idx - i * 150) * 2;
            const float* __restrict__ ob = o_s + i * DC;
            const float* __restrict__ wt = Wt_g + (size_t)i * DC * DD + d0;
            u64 acc = 0ull;
            #pragma unroll 8
            for (int k = 0; k < DC; ++k)
                fma2(acc, *(const u64*)(wt + (size_t)k * DD), splat2(ob[k]));
            *(u64*)(v_s + i * DD + d0) = acc;
        }
        __syncthreads();

        // ---------------- XPASS: warp-specialized, balanced pipeline ----------------
        if (t < 320) {
            // ===== wg0: prefetch + B only =====
            for (int idx = t; idx < AR_BUF / 4; idx += 320)
                cp16(sm + OFF_AR + idx * 4, xb + idx * 4);
            cp_commit();
            for (int idx = t; idx < AR_BUF / 4; idx += 320)
                cp16(sm + OFF_AR + AR_BUF + idx * 4, xb + AR_BUF + idx * 4);
            cp_commit();

            const int dB  = (w < 9) ? w * 32 : 288;
            const int n16 = (w < 9) ? 8 : 3;

            for (int k = 0; k < NTILE; ++k) {
                if (k == NTILE - 1) cp_wait<0>(); else cp_wait<1>();
                bar_sync(3, 320);                 // wg0 cp-data visible to all wg0
                const float* xs = sm + OFF_AR + (k % 3) * AR_BUF;
                float* bpk = bp + (k & 1) * 3520;

                // ---- B: b[i, j=lane] over this warp's d-chunk ----
                {
                    u64 acc[NC];
                    #pragma unroll
                    for (int i = 0; i < NC; ++i) acc[i] = 0ull;
                    const float* xrow = xs + lane * DD + dB;
                    for (int s = 0; s < n16; ++s) {
                        const u64x2_t xv = *(const u64x2_t*)(xrow + s * 4);
                        #pragma unroll
                        for (int i = 0; i < NC; ++i) {
                            const u64x2_t vv = *(const u64x2_t*)(v_s + i * DD + dB + s * 4);
                            fma2(acc[i], xv.x, vv.x);
                            fma2(acc[i], xv.y, vv.y);
                        }
                    }
                    #pragma unroll
                    for (int i = 0; i < NC; ++i)
                        bpk[w * 352 + lane * 11 + i] = fold2(acc[i]);
                }
                bar_arrive(1, 640);                 // B(k) ready for wg1
                if (k >= 1) bar_sync(2, 640);       // wait C(k-1): frees buf (k+2)%3
                if (k + 2 < NTILE) {
                    const float* gs = xb + (size_t)(k + 2) * AR_BUF;
                    float* dst = sm + OFF_AR + ((k + 2) % 3) * AR_BUF;
                    for (int idx = t; idx < AR_BUF / 4; idx += 320)
                        cp16(dst + idx * 4, gs + idx * 4);
                    cp_commit();
                }
            }
            bar_sync(2, 640);                       // consume C(last) arrive
        } else {
            // ===== wg1: softmax + C =====
            const int t2  = t - 320;                // 0..319, active < 300 for C
            const int jg  = t2 / 150;
            const int d0c = (t2 - jg * 150) * 2;
            const int j0  = jg * 16;
            u64 yacc[NC];
            #pragma unroll
            for (int i = 0; i < NC; ++i) yacc[i] = 0ull;

            for (int k = 0; k < NTILE; ++k) {
                bar_sync(1, 640);                   // wait B(k)
                const float* xs = sm + OFF_AR + (k % 3) * AR_BUF;
                const float* bpk = bp + (k & 1) * 3520;

                // ---- softmax over i per j (2 rounds: j 0..19, 20..31) ----
                #pragma unroll
                for (int rd = 0; rd < 2; ++rd) {
                    if (rd == 1 && t2 >= 192) break;      // warp-aligned exit
                    const int j  = rd * 20 + (t2 >> 4);
                    const int ii = t2 & 15;
                    float s;
                    if (ii < NC) {
                        s = 0.f;
                        #pragma unroll
                        for (int ww = 0; ww < 10; ++ww)
                            s += bpk[ww * 352 + j * 11 + ii];
                    } else s = -1e30f;
                    float m = s;
                    #pragma unroll
                    for (int kk = 8; kk > 0; kk >>= 1)
                        m = fmaxf(m, __shfl_xor_sync(0xffffffffu, m, kk, 16));
                    const float e = __expf(s - m);
                    float su = e;
                    #pragma unroll
                    for (int kk = 8; kk > 0; kk >>= 1)
                        su += __shfl_xor_sync(0xffffffffu, su, kk, 16);
                    if (ii < NC) cb[j * 12 + ii] = e * (1.0f / su);
                }
                bar_sync(4, 320);                   // cb visible across wg1

                // ---- C: yacc[i] += c[i,j] * x[j, d0c..d0c+1] ----
                if (t2 < 300) {
                    #pragma unroll
                    for (int jj = 0; jj < 16; ++jj) {
                        const int j = j0 + jj;
                        const u64 xv = *(const u64*)(xs + j * DD + d0c);
                        const float4 c0 = *(const float4*)(cb + j * 12);
                        const float4 c1 = *(const float4*)(cb + j * 12 + 4);
                        const float2 c2v = *(const float2*)(cb + j * 12 + 8);
                        fma2(yacc[0], xv, splat2(c0.x));
                        fma2(yacc[1], xv, splat2(c0.y));
                        fma2(yacc[2], xv, splat2(c0.z));
                        fma2(yacc[3], xv, splat2(c0.w));
                        fma2(yacc[4], xv, splat2(c1.x));
                        fma2(yacc[5], xv, splat2(c1.y));
                        fma2(yacc[6], xv, splat2(c1.z));
                        fma2(yacc[7], xv, splat2(c1.w));
                        fma2(yacc[8], xv, splat2(c2v.x));
                        fma2(yacc[9], xv, splat2(c2v.y));
                    }
                }
                bar_arrive(2, 640);                 // C(k) done
            }
            if (t2 < 300) {
                #pragma unroll
                for (int i = 0; i < NC; ++i)
                    *(u64*)(yp + jg * 3000 + i * DD + d0c) = yacc[i];
            }
        }
        __syncthreads();
        for (int idx = t; idx < NC * DD; idx += NT)
            y_s[idx] = yp[idx] + yp[3000 + idx];
        __syncthreads();
    }
}

extern "C" void kernel_launch(void* const* d_in, const int* in_sizes, int n_in,
                              void* d_out, int out_size)
{
    const float* x = (const float*)d_in[0];
    const float* W = (const float*)d_in[1];
    if (n_in >= 2 && in_sizes[0] < in_sizes[1]) {
        x = (const float*)d_in[1];
        W = (const float*)d_in[0];
    }
    float* out = (float*)d_out;

    static int attr_done = 0;
    if (!attr_done) {
        cudaFuncSetAttribute(caps_kernel, cudaFuncAttributeMaxDynamicSharedMemorySize,
                             SMEM_BYTES);
        attr_done = 1;
    }

    dim3 tb(32, 8);
    dim3 tg(MM / 32, (DD + 31) / 32);
    transpose_W<<<tg, tb>>>(W);
    caps_kernel<<<BB, NT, SMEM_BYTES>>>(x, W, out);
}